// round 12
// baseline (speedup 1.0000x reference)
#include <cuda_runtime.h>
#include <cuda_bf16.h>

#define NN 100000          // num nodes
#define DD 64              // signature dim

// ---------------- scratch (device globals: allocation-free) ----------------
__device__ float g_xw  [NN * DD];   // x * node_weight
__device__ float g_one [NN * DD];   // one_hop
__device__ float g_two [NN * DD];   // two_iter
__device__ float g_deg [NN];
__device__ float g_deg2[NN];
__device__ int   g_rowptr[NN + 1];

// ---------------- kernel 1: xw = x * w ----------------
__global__ void xw_kernel(const float* __restrict__ x,
                          const float* __restrict__ w,
                          int n_elems4) {
    int i = blockIdx.x * blockDim.x + threadIdx.x;
    if (i >= n_elems4) return;
    float4 v = ((const float4*)x)[i];
    float ww = __ldg(&w[i >> 4]);           // 16 float4 per 64-wide row
    v.x *= ww; v.y *= ww; v.z *= ww; v.w *= ww;
    ((float4*)g_xw)[i] = v;
}

// ---------------- kernel 2: CSR row_ptr (binary search, sorted adj_row) + deg ----
__global__ void rowptr_kernel(const int* __restrict__ adj_row, int nadj, int n) {
    int r = blockIdx.x * blockDim.x + threadIdx.x;
    if (r > n) return;
    int lo = 0, hi = nadj;
    while (lo < hi) {
        int mid = (lo + hi) >> 1;
        if (__ldg(&adj_row[mid]) < r) lo = mid + 1; else hi = mid;
    }
    g_rowptr[r] = lo;
    if (r < n) {
        int lo2 = lo, hi2 = nadj;
        while (lo2 < hi2) {
            int mid = (lo2 + hi2) >> 1;
            if (__ldg(&adj_row[mid]) < r + 1) lo2 = mid + 1; else hi2 = mid;
        }
        g_deg[r] = (float)(lo2 - lo);
    }
}

// ---------------- SpMM: 16-lane subwarp per node, lane = 4 dims (float4) -----
// 8 gathers in flight before accumulation (MLP=8 per lane).
template <bool WITH_DEG2>
__device__ __forceinline__ void spmm_sub_body(const float4* __restrict__ src4,
                                              float4*       __restrict__ dst4,
                                              const int*    __restrict__ adj_col,
                                              int n) {
    const int tid  = blockIdx.x * blockDim.x + threadIdx.x;
    const int node = tid >> 4;
    const int lane = threadIdx.x & 15;     // 0..15 within subwarp
    if (node >= n) return;

    const unsigned smask = 0xffffu << (threadIdx.x & 16);  // this subwarp's mask

    const int start = g_rowptr[node];
    const int end   = g_rowptr[node + 1];

    float4 a0 = {0,0,0,0}, a1 = {0,0,0,0}, a2 = {0,0,0,0}, a3 = {0,0,0,0};
    float dsum = 0.f;

    for (int base = start; base < end; base += 16) {
        const int chunk = min(16, end - base);
        int c = 0;
        if (lane < chunk) {
            c = __ldg(&adj_col[base + lane]);
            if (WITH_DEG2) dsum += __ldg(&g_deg[c]);
        }
        int j = 0;
        // 8 loads in flight, then accumulate
        for (; j + 8 <= chunk; j += 8) {
            int c0 = __shfl_sync(smask, c, j,     16);
            int c1 = __shfl_sync(smask, c, j + 1, 16);
            int c2 = __shfl_sync(smask, c, j + 2, 16);
            int c3 = __shfl_sync(smask, c, j + 3, 16);
            int c4 = __shfl_sync(smask, c, j + 4, 16);
            int c5 = __shfl_sync(smask, c, j + 5, 16);
            int c6 = __shfl_sync(smask, c, j + 6, 16);
            int c7 = __shfl_sync(smask, c, j + 7, 16);
            float4 v0 = __ldg(&src4[c0 * 16 + lane]);
            float4 v1 = __ldg(&src4[c1 * 16 + lane]);
            float4 v2 = __ldg(&src4[c2 * 16 + lane]);
            float4 v3 = __ldg(&src4[c3 * 16 + lane]);
            float4 v4 = __ldg(&src4[c4 * 16 + lane]);
            float4 v5 = __ldg(&src4[c5 * 16 + lane]);
            float4 v6 = __ldg(&src4[c6 * 16 + lane]);
            float4 v7 = __ldg(&src4[c7 * 16 + lane]);
            a0.x += v0.x; a0.y += v0.y; a0.z += v0.z; a0.w += v0.w;
            a1.x += v1.x; a1.y += v1.y; a1.z += v1.z; a1.w += v1.w;
            a2.x += v2.x; a2.y += v2.y; a2.z += v2.z; a2.w += v2.w;
            a3.x += v3.x; a3.y += v3.y; a3.z += v3.z; a3.w += v3.w;
            a0.x += v4.x; a0.y += v4.y; a0.z += v4.z; a0.w += v4.w;
            a1.x += v5.x; a1.y += v5.y; a1.z += v5.z; a1.w += v5.w;
            a2.x += v6.x; a2.y += v6.y; a2.z += v6.z; a2.w += v6.w;
            a3.x += v7.x; a3.y += v7.y; a3.z += v7.z; a3.w += v7.w;
        }
        for (; j + 4 <= chunk; j += 4) {
            int c0 = __shfl_sync(smask, c, j,     16);
            int c1 = __shfl_sync(smask, c, j + 1, 16);
            int c2 = __shfl_sync(smask, c, j + 2, 16);
            int c3 = __shfl_sync(smask, c, j + 3, 16);
            float4 v0 = __ldg(&src4[c0 * 16 + lane]);
            float4 v1 = __ldg(&src4[c1 * 16 + lane]);
            float4 v2 = __ldg(&src4[c2 * 16 + lane]);
            float4 v3 = __ldg(&src4[c3 * 16 + lane]);
            a0.x += v0.x; a0.y += v0.y; a0.z += v0.z; a0.w += v0.w;
            a1.x += v1.x; a1.y += v1.y; a1.z += v1.z; a1.w += v1.w;
            a2.x += v2.x; a2.y += v2.y; a2.z += v2.z; a2.w += v2.w;
            a3.x += v3.x; a3.y += v3.y; a3.z += v3.z; a3.w += v3.w;
        }
        for (; j < chunk; ++j) {
            int cj = __shfl_sync(smask, c, j, 16);
            float4 v = __ldg(&src4[cj * 16 + lane]);
            a0.x += v.x; a0.y += v.y; a0.z += v.z; a0.w += v.w;
        }
    }
    float4 res;
    res.x = (a0.x + a1.x) + (a2.x + a3.x);
    res.y = (a0.y + a1.y) + (a2.y + a3.y);
    res.z = (a0.z + a1.z) + (a2.z + a3.z);
    res.w = (a0.w + a1.w) + (a2.w + a3.w);
    dst4[node * 16 + lane] = res;

    if (WITH_DEG2) {
        #pragma unroll
        for (int o = 8; o > 0; o >>= 1)
            dsum += __shfl_xor_sync(smask, dsum, o, 16);
        if (lane == 0)
            g_deg2[node] = fmaxf(dsum - g_deg[node] - 1.0f, 0.0f);
    }
}

__global__ void __launch_bounds__(256) spmm_one_kernel(const int* __restrict__ adj_col, int n) {
    spmm_sub_body<true>((const float4*)g_xw, (float4*)g_one, adj_col, n);
}
__global__ void __launch_bounds__(256) spmm_two_kernel(const int* __restrict__ adj_col, int n) {
    spmm_sub_body<false>((const float4*)g_one, (float4*)g_two, adj_col, n);
}

// ---------------- edge features: 8-lane subwarp per edge, 2x float4/lane -----
__device__ __forceinline__ float dot4(float4 a, float4 b) {
    return a.x * b.x + a.y * b.y + a.z * b.z + a.w * b.w;
}
__device__ __forceinline__ float4 sub3(float4 t, float4 o, float4 x) {
    float4 r; r.x = t.x - o.x - x.x; r.y = t.y - o.y - x.y;
    r.z = t.z - o.z - x.z; r.w = t.w - o.w - x.w; return r;
}
__device__ __forceinline__ float4 fnma(float4 t, float d, float4 x) {
    float4 r; r.x = t.x - d * x.x; r.y = t.y - d * x.y;
    r.z = t.z - d * x.z; r.w = t.w - d * x.w; return r;
}

__global__ void __launch_bounds__(256) edge_kernel(const int* __restrict__ edges, int ne,
                            float* __restrict__ out) {
    const int ge = (blockIdx.x * blockDim.x + threadIdx.x) >> 3;  // edge id
    const int l  = threadIdx.x & 7;                               // 0..7
    if (ge >= ne) return;

    const unsigned emask = 0xffu << (threadIdx.x & 24);           // 8-lane mask

    const int u = __ldg(&edges[ge]);
    const int v = __ldg(&edges[ne + ge]);

    const float4* xu_p = (const float4*)(g_xw  + u * DD);
    const float4* xv_p = (const float4*)(g_xw  + v * DD);
    const float4* u1_p = (const float4*)(g_one + u * DD);
    const float4* v1_p = (const float4*)(g_one + v * DD);
    const float4* tu_p = (const float4*)(g_two + u * DD);
    const float4* tv_p = (const float4*)(g_two + v * DD);

    // Front-batch ALL loads (12 LDG.128 + 4 scalar) before any math: MLP=12.
    float4 xuA = __ldg(&xu_p[l]), xuB = __ldg(&xu_p[l + 8]);
    float4 xvA = __ldg(&xv_p[l]), xvB = __ldg(&xv_p[l + 8]);
    float4 u1A = __ldg(&u1_p[l]), u1B = __ldg(&u1_p[l + 8]);
    float4 v1A = __ldg(&v1_p[l]), v1B = __ldg(&v1_p[l + 8]);
    float4 tuA = __ldg(&tu_p[l]), tuB = __ldg(&tu_p[l + 8]);
    float4 tvA = __ldg(&tv_p[l]), tvB = __ldg(&tv_p[l + 8]);
    const float du  = __ldg(&g_deg [u]), dv  = __ldg(&g_deg [v]);
    const float du2 = __ldg(&g_deg2[u]), dv2 = __ldg(&g_deg2[v]);

    float4 u2A = sub3(tuA, u1A, xuA), u2B = sub3(tuB, u1B, xuB);
    float4 v2A = sub3(tvA, v1A, xvA), v2B = sub3(tvB, v1B, xvB);
    float4 auA = fnma(tuA, du, xuA),  auB = fnma(tuB, du, xuB);
    float4 avA = fnma(tvA, dv, xvA),  avB = fnma(tvB, dv, xvB);

    float c11  = dot4(u1A, v1A) + dot4(u1B, v1B);
    float c12  = dot4(u1A, v2A) + dot4(u1B, v2B);
    float c21  = dot4(u2A, v1A) + dot4(u2B, v1B);
    float c22  = dot4(u2A, v2A) + dot4(u2B, v2B);
    float cb12 = dot4(u1A, tvA) + dot4(u1B, tvB);
    float cb21 = dot4(tuA, v1A) + dot4(tuB, v1B);
    float cb22 = dot4(auA, avA) + dot4(auB, avB);
    float cs12 = dot4(u1A, tuA) + dot4(u1B, tuB);
    float cs21 = dot4(v1A, tvA) + dot4(v1B, tvB);

    #pragma unroll
    for (int o = 4; o > 0; o >>= 1) {
        c11  += __shfl_xor_sync(emask, c11,  o, 8);
        c12  += __shfl_xor_sync(emask, c12,  o, 8);
        c21  += __shfl_xor_sync(emask, c21,  o, 8);
        c22  += __shfl_xor_sync(emask, c22,  o, 8);
        cb12 += __shfl_xor_sync(emask, cb12, o, 8);
        cb21 += __shfl_xor_sync(emask, cb21, o, 8);
        cb22 += __shfl_xor_sync(emask, cb22, o, 8);
        cs12 += __shfl_xor_sync(emask, cs12, o, 8);
        cs21 += __shfl_xor_sync(emask, cs21, o, 8);
    }

    if (l == 0) {
        float c1inf = du  + dv  - 2.0f * c11 - c12 - c21;
        float c2inf = du2 + dv2 - 2.0f * c22 - c12 - c21;
        float* o15 = out + (size_t)ge * 15;
        o15[0]  = c11;   o15[1]  = c12;  o15[2]  = c21;  o15[3]  = c22;
        o15[4]  = c1inf; o15[5]  = c2inf;
        o15[6]  = cb12;  o15[7]  = cb21; o15[8]  = cb22;
        o15[9]  = cs12;  o15[10] = cs21;
        o15[11] = du;    o15[12] = dv;   o15[13] = du2;  o15[14] = dv2;
    }
}

// ---------------- launch (pure kernel launches: graph-capturable) ----------
extern "C" void kernel_launch(void* const* d_in, const int* in_sizes, int n_in,
                              void* d_out, int out_size) {
    const float* x  = (const float*)d_in[0];
    const float* w  = (const float*)d_in[1];
    const int*   ed = (const int*)  d_in[2];
    const int*   ar = (const int*)  d_in[3];
    const int*   ac = (const int*)  d_in[4];

    const int n    = in_sizes[1];            // 100000
    const int ne   = in_sizes[2] / 2;        // 262144
    const int nadj = in_sizes[3];            // 1600000

    // 1) xw = x * node_weight
    {
        int n4 = (n * DD) / 4;
        xw_kernel<<<(n4 + 255) / 256, 256>>>(x, w, n4);
    }
    // 2) CSR rowptr + deg
    rowptr_kernel<<<(n + 1 + 255) / 256, 256>>>(ar, nadj, n);
    // 3) one_hop = A @ xw (+ deg2); 16 lanes/node -> 16 nodes per 256-thr block
    {
        int blocks = (n + 15) / 16;
        spmm_one_kernel<<<blocks, 256>>>(ac, n);
    }
    // 4) two_iter = A @ one_hop
    {
        int blocks = (n + 15) / 16;
        spmm_two_kernel<<<blocks, 256>>>(ac, n);
    }
    // 5) per-edge features; 8 lanes/edge -> 32 edges per 256-thr block
    {
        int blocks = (ne + 31) / 32;
        edge_kernel<<<blocks, 256>>>(ed, ne, (float*)d_out);
    }
}

// round 13
// speedup vs baseline: 1.5440x; 1.5440x over previous
#include <cuda_runtime.h>
#include <cuda_bf16.h>

#define NN 100000          // num nodes
#define DD 64              // signature dim

// ---------------- scratch (device globals: allocation-free) ----------------
__device__ float g_xw  [NN * DD];   // x * node_weight
__device__ float g_one [NN * DD];   // one_hop
__device__ float g_two [NN * DD];   // two_iter
__device__ float g_deg [NN];
__device__ float g_deg2[NN];
__device__ int   g_rowptr[NN + 1];

// ---------------- kernel 1: xw = x * w ----------------
__global__ void xw_kernel(const float* __restrict__ x,
                          const float* __restrict__ w,
                          int n_elems4) {
    int i = blockIdx.x * blockDim.x + threadIdx.x;
    if (i >= n_elems4) return;
    float4 v = ((const float4*)x)[i];
    float ww = __ldg(&w[i >> 4]);           // 16 float4 per 64-wide row
    v.x *= ww; v.y *= ww; v.z *= ww; v.w *= ww;
    ((float4*)g_xw)[i] = v;
}

// ---------------- kernel 2: CSR row_ptr (binary search, sorted adj_row) + deg ----
__global__ void rowptr_kernel(const int* __restrict__ adj_row, int nadj, int n) {
    int r = blockIdx.x * blockDim.x + threadIdx.x;
    if (r > n) return;
    int lo = 0, hi = nadj;
    while (lo < hi) {
        int mid = (lo + hi) >> 1;
        if (__ldg(&adj_row[mid]) < r) lo = mid + 1; else hi = mid;
    }
    g_rowptr[r] = lo;
    if (r < n) {
        int lo2 = lo, hi2 = nadj;
        while (lo2 < hi2) {
            int mid = (lo2 + hi2) >> 1;
            if (__ldg(&adj_row[mid]) < r + 1) lo2 = mid + 1; else hi2 = mid;
        }
        g_deg[r] = (float)(lo2 - lo);
    }
}

// ---------------- SpMM: 16-lane subwarp per node, lane = 4 dims (float4) -----
// MLP=4 in-flight gathers (proven best on B300 — MLP=8 regressed via
// cross-CTA L1tex-queue contention + occupancy cliff). TWO float4
// accumulators instead of four to cut register pressure (~48 -> ~40 regs)
// and gain a 6th resident CTA per SM.
template <bool WITH_DEG2>
__device__ __forceinline__ void spmm_sub_body(const float4* __restrict__ src4,
                                              float4*       __restrict__ dst4,
                                              const int*    __restrict__ adj_col,
                                              int n) {
    const int tid  = blockIdx.x * blockDim.x + threadIdx.x;
    const int node = tid >> 4;
    const int lane = threadIdx.x & 15;     // 0..15 within subwarp
    if (node >= n) return;

    const unsigned smask = 0xffffu << (threadIdx.x & 16);  // this subwarp's mask

    const int start = g_rowptr[node];
    const int end   = g_rowptr[node + 1];

    float4 a0 = {0,0,0,0}, a1 = {0,0,0,0};
    float dsum = 0.f;

    for (int base = start; base < end; base += 16) {
        const int chunk = min(16, end - base);
        int c = 0;
        if (lane < chunk) {
            c = __ldg(&adj_col[base + lane]);
            if (WITH_DEG2) dsum += __ldg(&g_deg[c]);
        }
        int j = 0;
        for (; j + 4 <= chunk; j += 4) {
            int c0 = __shfl_sync(smask, c, j,     16);
            int c1 = __shfl_sync(smask, c, j + 1, 16);
            int c2 = __shfl_sync(smask, c, j + 2, 16);
            int c3 = __shfl_sync(smask, c, j + 3, 16);
            float4 v0 = __ldg(&src4[c0 * 16 + lane]);
            float4 v1 = __ldg(&src4[c1 * 16 + lane]);
            float4 v2 = __ldg(&src4[c2 * 16 + lane]);
            float4 v3 = __ldg(&src4[c3 * 16 + lane]);
            a0.x += v0.x; a0.y += v0.y; a0.z += v0.z; a0.w += v0.w;
            a1.x += v1.x; a1.y += v1.y; a1.z += v1.z; a1.w += v1.w;
            a0.x += v2.x; a0.y += v2.y; a0.z += v2.z; a0.w += v2.w;
            a1.x += v3.x; a1.y += v3.y; a1.z += v3.z; a1.w += v3.w;
        }
        for (; j < chunk; ++j) {
            int cj = __shfl_sync(smask, c, j, 16);
            float4 v = __ldg(&src4[cj * 16 + lane]);
            a0.x += v.x; a0.y += v.y; a0.z += v.z; a0.w += v.w;
        }
    }
    float4 res;
    res.x = a0.x + a1.x;
    res.y = a0.y + a1.y;
    res.z = a0.z + a1.z;
    res.w = a0.w + a1.w;
    dst4[node * 16 + lane] = res;

    if (WITH_DEG2) {
        #pragma unroll
        for (int o = 8; o > 0; o >>= 1)
            dsum += __shfl_xor_sync(smask, dsum, o, 16);
        if (lane == 0)
            g_deg2[node] = fmaxf(dsum - g_deg[node] - 1.0f, 0.0f);
    }
}

__global__ void __launch_bounds__(256) spmm_one_kernel(const int* __restrict__ adj_col, int n) {
    spmm_sub_body<true>((const float4*)g_xw, (float4*)g_one, adj_col, n);
}
__global__ void __launch_bounds__(256) spmm_two_kernel(const int* __restrict__ adj_col, int n) {
    spmm_sub_body<false>((const float4*)g_one, (float4*)g_two, adj_col, n);
}

// ---------------- edge features: 8-lane subwarp per edge, 2x float4/lane -----
__device__ __forceinline__ float dot4(float4 a, float4 b) {
    return a.x * b.x + a.y * b.y + a.z * b.z + a.w * b.w;
}
__device__ __forceinline__ float4 sub3(float4 t, float4 o, float4 x) {
    float4 r; r.x = t.x - o.x - x.x; r.y = t.y - o.y - x.y;
    r.z = t.z - o.z - x.z; r.w = t.w - o.w - x.w; return r;
}
__device__ __forceinline__ float4 fnma(float4 t, float d, float4 x) {
    float4 r; r.x = t.x - d * x.x; r.y = t.y - d * x.y;
    r.z = t.z - d * x.z; r.w = t.w - d * x.w; return r;
}

__global__ void __launch_bounds__(256) edge_kernel(const int* __restrict__ edges, int ne,
                            float* __restrict__ out) {
    const int ge = (blockIdx.x * blockDim.x + threadIdx.x) >> 3;  // edge id
    const int l  = threadIdx.x & 7;                               // 0..7
    if (ge >= ne) return;

    const unsigned emask = 0xffu << (threadIdx.x & 24);           // 8-lane mask

    const int u = __ldg(&edges[ge]);
    const int v = __ldg(&edges[ne + ge]);

    const float4* xu_p = (const float4*)(g_xw  + u * DD);
    const float4* xv_p = (const float4*)(g_xw  + v * DD);
    const float4* u1_p = (const float4*)(g_one + u * DD);
    const float4* v1_p = (const float4*)(g_one + v * DD);
    const float4* tu_p = (const float4*)(g_two + u * DD);
    const float4* tv_p = (const float4*)(g_two + v * DD);

    float4 xuA = __ldg(&xu_p[l]), xuB = __ldg(&xu_p[l + 8]);
    float4 xvA = __ldg(&xv_p[l]), xvB = __ldg(&xv_p[l + 8]);
    float4 u1A = __ldg(&u1_p[l]), u1B = __ldg(&u1_p[l + 8]);
    float4 v1A = __ldg(&v1_p[l]), v1B = __ldg(&v1_p[l + 8]);
    float4 tuA = __ldg(&tu_p[l]), tuB = __ldg(&tu_p[l + 8]);
    float4 tvA = __ldg(&tv_p[l]), tvB = __ldg(&tv_p[l + 8]);
    const float du  = __ldg(&g_deg [u]), dv  = __ldg(&g_deg [v]);
    const float du2 = __ldg(&g_deg2[u]), dv2 = __ldg(&g_deg2[v]);

    float4 u2A = sub3(tuA, u1A, xuA), u2B = sub3(tuB, u1B, xuB);
    float4 v2A = sub3(tvA, v1A, xvA), v2B = sub3(tvB, v1B, xvB);
    float4 auA = fnma(tuA, du, xuA),  auB = fnma(tuB, du, xuB);
    float4 avA = fnma(tvA, dv, xvA),  avB = fnma(tvB, dv, xvB);

    float c11  = dot4(u1A, v1A) + dot4(u1B, v1B);
    float c12  = dot4(u1A, v2A) + dot4(u1B, v2B);
    float c21  = dot4(u2A, v1A) + dot4(u2B, v1B);
    float c22  = dot4(u2A, v2A) + dot4(u2B, v2B);
    float cb12 = dot4(u1A, tvA) + dot4(u1B, tvB);
    float cb21 = dot4(tuA, v1A) + dot4(tuB, v1B);
    float cb22 = dot4(auA, avA) + dot4(auB, avB);
    float cs12 = dot4(u1A, tuA) + dot4(u1B, tuB);
    float cs21 = dot4(v1A, tvA) + dot4(v1B, tvB);

    #pragma unroll
    for (int o = 4; o > 0; o >>= 1) {
        c11  += __shfl_xor_sync(emask, c11,  o, 8);
        c12  += __shfl_xor_sync(emask, c12,  o, 8);
        c21  += __shfl_xor_sync(emask, c21,  o, 8);
        c22  += __shfl_xor_sync(emask, c22,  o, 8);
        cb12 += __shfl_xor_sync(emask, cb12, o, 8);
        cb21 += __shfl_xor_sync(emask, cb21, o, 8);
        cb22 += __shfl_xor_sync(emask, cb22, o, 8);
        cs12 += __shfl_xor_sync(emask, cs12, o, 8);
        cs21 += __shfl_xor_sync(emask, cs21, o, 8);
    }

    if (l == 0) {
        float c1inf = du  + dv  - 2.0f * c11 - c12 - c21;
        float c2inf = du2 + dv2 - 2.0f * c22 - c12 - c21;
        float* o15 = out + (size_t)ge * 15;
        o15[0]  = c11;   o15[1]  = c12;  o15[2]  = c21;  o15[3]  = c22;
        o15[4]  = c1inf; o15[5]  = c2inf;
        o15[6]  = cb12;  o15[7]  = cb21; o15[8]  = cb22;
        o15[9]  = cs12;  o15[10] = cs21;
        o15[11] = du;    o15[12] = dv;   o15[13] = du2;  o15[14] = dv2;
    }
}

// ---------------- launch (pure kernel launches: graph-capturable) ----------
extern "C" void kernel_launch(void* const* d_in, const int* in_sizes, int n_in,
                              void* d_out, int out_size) {
    const float* x  = (const float*)d_in[0];
    const float* w  = (const float*)d_in[1];
    const int*   ed = (const int*)  d_in[2];
    const int*   ar = (const int*)  d_in[3];
    const int*   ac = (const int*)  d_in[4];

    const int n    = in_sizes[1];            // 100000
    const int ne   = in_sizes[2] / 2;        // 262144
    const int nadj = in_sizes[3];            // 1600000

    // 1) xw = x * node_weight
    {
        int n4 = (n * DD) / 4;
        xw_kernel<<<(n4 + 255) / 256, 256>>>(x, w, n4);
    }
    // 2) CSR rowptr + deg
    rowptr_kernel<<<(n + 1 + 255) / 256, 256>>>(ar, nadj, n);
    // 3) one_hop = A @ xw (+ deg2); 16 lanes/node -> 16 nodes per 256-thr block
    {
        int blocks = (n + 15) / 16;
        spmm_one_kernel<<<blocks, 256>>>(ac, n);
    }
    // 4) two_iter = A @ one_hop
    {
        int blocks = (n + 15) / 16;
        spmm_two_kernel<<<blocks, 256>>>(ac, n);
    }
    // 5) per-edge features; 8 lanes/edge -> 32 edges per 256-thr block
    {
        int blocks = (ne + 31) / 32;
        edge_kernel<<<blocks, 256>>>(ed, ne, (float*)d_out);
    }
}

// round 15
// speedup vs baseline: 1.5883x; 1.0287x over previous
#include <cuda_runtime.h>
#include <cuda_bf16.h>

#define NN 100000          // num nodes
#define DD 64              // signature dim

// ---------------- scratch (device globals: allocation-free) ----------------
__device__ float g_xw  [NN * DD];   // x * node_weight
__device__ float g_one [NN * DD];   // one_hop
__device__ float g_two [NN * DD];   // two_iter
__device__ float g_deg [NN];
__device__ float g_deg2[NN];
__device__ int   g_rowptr[NN + 1];

// ---------------- kernel 1: xw = x * w ----------------
__global__ void xw_kernel(const float* __restrict__ x,
                          const float* __restrict__ w,
                          int n_elems4) {
    int i = blockIdx.x * blockDim.x + threadIdx.x;
    if (i >= n_elems4) return;
    float4 v = ((const float4*)x)[i];
    float ww = __ldg(&w[i >> 4]);           // 16 float4 per 64-wide row
    v.x *= ww; v.y *= ww; v.z *= ww; v.w *= ww;
    ((float4*)g_xw)[i] = v;
}

// ---------------- kernel 2: CSR row_ptr (binary search, sorted adj_row) + deg ----
__global__ void rowptr_kernel(const int* __restrict__ adj_row, int nadj, int n) {
    int r = blockIdx.x * blockDim.x + threadIdx.x;
    if (r > n) return;
    int lo = 0, hi = nadj;
    while (lo < hi) {
        int mid = (lo + hi) >> 1;
        if (__ldg(&adj_row[mid]) < r) lo = mid + 1; else hi = mid;
    }
    g_rowptr[r] = lo;
    if (r < n) {
        int lo2 = lo, hi2 = nadj;
        while (lo2 < hi2) {
            int mid = (lo2 + hi2) >> 1;
            if (__ldg(&adj_row[mid]) < r + 1) lo2 = mid + 1; else hi2 = mid;
        }
        g_deg[r] = (float)(lo2 - lo);
    }
}

// ---------------- SpMM: 16-lane subwarp per node, lane = 4 dims (float4) -----
// MLP=4 in-flight gathers, two accumulators (36 regs, occ 61%) — measured at
// the LTS bandwidth cap (~6000 B/cyc); do not touch.
template <bool WITH_DEG2>
__device__ __forceinline__ void spmm_sub_body(const float4* __restrict__ src4,
                                              float4*       __restrict__ dst4,
                                              const int*    __restrict__ adj_col,
                                              int n) {
    const int tid  = blockIdx.x * blockDim.x + threadIdx.x;
    const int node = tid >> 4;
    const int lane = threadIdx.x & 15;     // 0..15 within subwarp
    if (node >= n) return;

    const unsigned smask = 0xffffu << (threadIdx.x & 16);  // this subwarp's mask

    const int start = g_rowptr[node];
    const int end   = g_rowptr[node + 1];

    float4 a0 = {0,0,0,0}, a1 = {0,0,0,0};
    float dsum = 0.f;

    for (int base = start; base < end; base += 16) {
        const int chunk = min(16, end - base);
        int c = 0;
        if (lane < chunk) {
            c = __ldg(&adj_col[base + lane]);
            if (WITH_DEG2) dsum += __ldg(&g_deg[c]);
        }
        int j = 0;
        for (; j + 4 <= chunk; j += 4) {
            int c0 = __shfl_sync(smask, c, j,     16);
            int c1 = __shfl_sync(smask, c, j + 1, 16);
            int c2 = __shfl_sync(smask, c, j + 2, 16);
            int c3 = __shfl_sync(smask, c, j + 3, 16);
            float4 v0 = __ldg(&src4[c0 * 16 + lane]);
            float4 v1 = __ldg(&src4[c1 * 16 + lane]);
            float4 v2 = __ldg(&src4[c2 * 16 + lane]);
            float4 v3 = __ldg(&src4[c3 * 16 + lane]);
            a0.x += v0.x; a0.y += v0.y; a0.z += v0.z; a0.w += v0.w;
            a1.x += v1.x; a1.y += v1.y; a1.z += v1.z; a1.w += v1.w;
            a0.x += v2.x; a0.y += v2.y; a0.z += v2.z; a0.w += v2.w;
            a1.x += v3.x; a1.y += v3.y; a1.z += v3.z; a1.w += v3.w;
        }
        for (; j < chunk; ++j) {
            int cj = __shfl_sync(smask, c, j, 16);
            float4 v = __ldg(&src4[cj * 16 + lane]);
            a0.x += v.x; a0.y += v.y; a0.z += v.z; a0.w += v.w;
        }
    }
    float4 res;
    res.x = a0.x + a1.x;
    res.y = a0.y + a1.y;
    res.z = a0.z + a1.z;
    res.w = a0.w + a1.w;
    dst4[node * 16 + lane] = res;

    if (WITH_DEG2) {
        #pragma unroll
        for (int o = 8; o > 0; o >>= 1)
            dsum += __shfl_xor_sync(smask, dsum, o, 16);
        if (lane == 0)
            g_deg2[node] = fmaxf(dsum - g_deg[node] - 1.0f, 0.0f);
    }
}

__global__ void __launch_bounds__(256) spmm_one_kernel(const int* __restrict__ adj_col, int n) {
    spmm_sub_body<true>((const float4*)g_xw, (float4*)g_one, adj_col, n);
}
__global__ void __launch_bounds__(256) spmm_two_kernel(const int* __restrict__ adj_col, int n) {
    spmm_sub_body<false>((const float4*)g_one, (float4*)g_two, adj_col, n);
}

// ---------------- edge features: 8-lane subwarp per edge, TWO-PHASE loads ----
// Phase h covers dims [h*32, h*32+32): 6 float4 loads live at a time instead
// of 12 -> roughly halves register pressure, doubling resident CTAs.
__device__ __forceinline__ float dot4(float4 a, float4 b) {
    return a.x * b.x + a.y * b.y + a.z * b.z + a.w * b.w;
}
__device__ __forceinline__ float4 sub3(float4 t, float4 o, float4 x) {
    float4 r; r.x = t.x - o.x - x.x; r.y = t.y - o.y - x.y;
    r.z = t.z - o.z - x.z; r.w = t.w - o.w - x.w; return r;
}
__device__ __forceinline__ float4 fnma(float4 t, float d, float4 x) {
    float4 r; r.x = t.x - d * x.x; r.y = t.y - d * x.y;
    r.z = t.z - d * x.z; r.w = t.w - d * x.w; return r;
}

__global__ void __launch_bounds__(256) edge_kernel(const int* __restrict__ edges, int ne,
                            float* __restrict__ out) {
    const int ge = (blockIdx.x * blockDim.x + threadIdx.x) >> 3;  // edge id
    const int l  = threadIdx.x & 7;                               // 0..7
    if (ge >= ne) return;

    const unsigned emask = 0xffu << (threadIdx.x & 24);           // 8-lane mask

    const int u = __ldg(&edges[ge]);
    const int v = __ldg(&edges[ne + ge]);

    const float du  = __ldg(&g_deg [u]), dv  = __ldg(&g_deg [v]);
    const float du2 = __ldg(&g_deg2[u]), dv2 = __ldg(&g_deg2[v]);

    const float4* xu_p = (const float4*)(g_xw  + u * DD);
    const float4* xv_p = (const float4*)(g_xw  + v * DD);
    const float4* u1_p = (const float4*)(g_one + u * DD);
    const float4* v1_p = (const float4*)(g_one + v * DD);
    const float4* tu_p = (const float4*)(g_two + u * DD);
    const float4* tv_p = (const float4*)(g_two + v * DD);

    float c11 = 0.f, c12 = 0.f, c21 = 0.f, c22 = 0.f;
    float cb12 = 0.f, cb21 = 0.f, cb22 = 0.f, cs12 = 0.f, cs21 = 0.f;

    #pragma unroll 1
    for (int h = 0; h < 2; ++h) {
        const int idx = l + h * 8;
        float4 xu = __ldg(&xu_p[idx]);
        float4 xv = __ldg(&xv_p[idx]);
        float4 u1 = __ldg(&u1_p[idx]);
        float4 v1 = __ldg(&v1_p[idx]);
        float4 tu = __ldg(&tu_p[idx]);
        float4 tv = __ldg(&tv_p[idx]);

        float4 u2 = sub3(tu, u1, xu);
        float4 v2 = sub3(tv, v1, xv);
        float4 au = fnma(tu, du, xu);
        float4 av = fnma(tv, dv, xv);

        c11  += dot4(u1, v1);
        c12  += dot4(u1, v2);
        c21  += dot4(u2, v1);
        c22  += dot4(u2, v2);
        cb12 += dot4(u1, tv);
        cb21 += dot4(tu, v1);
        cb22 += dot4(au, av);
        cs12 += dot4(u1, tu);
        cs21 += dot4(v1, tv);
    }

    #pragma unroll
    for (int o = 4; o > 0; o >>= 1) {
        c11  += __shfl_xor_sync(emask, c11,  o, 8);
        c12  += __shfl_xor_sync(emask, c12,  o, 8);
        c21  += __shfl_xor_sync(emask, c21,  o, 8);
        c22  += __shfl_xor_sync(emask, c22,  o, 8);
        cb12 += __shfl_xor_sync(emask, cb12, o, 8);
        cb21 += __shfl_xor_sync(emask, cb21, o, 8);
        cb22 += __shfl_xor_sync(emask, cb22, o, 8);
        cs12 += __shfl_xor_sync(emask, cs12, o, 8);
        cs21 += __shfl_xor_sync(emask, cs21, o, 8);
    }

    if (l == 0) {
        float c1inf = du  + dv  - 2.0f * c11 - c12 - c21;
        float c2inf = du2 + dv2 - 2.0f * c22 - c12 - c21;
        float* o15 = out + (size_t)ge * 15;
        o15[0]  = c11;   o15[1]  = c12;  o15[2]  = c21;  o15[3]  = c22;
        o15[4]  = c1inf; o15[5]  = c2inf;
        o15[6]  = cb12;  o15[7]  = cb21; o15[8]  = cb22;
        o15[9]  = cs12;  o15[10] = cs21;
        o15[11] = du;    o15[12] = dv;   o15[13] = du2;  o15[14] = dv2;
    }
}

// ---------------- launch (pure kernel launches: graph-capturable) ----------
extern "C" void kernel_launch(void* const* d_in, const int* in_sizes, int n_in,
                              void* d_out, int out_size) {
    const float* x  = (const float*)d_in[0];
    const float* w  = (const float*)d_in[1];
    const int*   ed = (const int*)  d_in[2];
    const int*   ar = (const int*)  d_in[3];
    const int*   ac = (const int*)  d_in[4];

    const int n    = in_sizes[1];            // 100000
    const int ne   = in_sizes[2] / 2;        // 262144
    const int nadj = in_sizes[3];            // 1600000

    // 1) xw = x * node_weight
    {
        int n4 = (n * DD) / 4;
        xw_kernel<<<(n4 + 255) / 256, 256>>>(x, w, n4);
    }
    // 2) CSR rowptr + deg
    rowptr_kernel<<<(n + 1 + 255) / 256, 256>>>(ar, nadj, n);
    // 3) one_hop = A @ xw (+ deg2); 16 lanes/node -> 16 nodes per 256-thr block
    {
        int blocks = (n + 15) / 16;
        spmm_one_kernel<<<blocks, 256>>>(ac, n);
    }
    // 4) two_iter = A @ one_hop
    {
        int blocks = (n + 15) / 16;
        spmm_two_kernel<<<blocks, 256>>>(ac, n);
    }
    // 5) per-edge features; 8 lanes/edge -> 32 edges per 256-thr block
    {
        int blocks = (ne + 31) / 32;
        edge_kernel<<<blocks, 256>>>(ed, ne, (float*)d_out);
    }
}